// round 7
// baseline (speedup 1.0000x reference)
#include <cuda_runtime.h>
#include <cuda_bf16.h>

// Problem constants (fixed by the dataset)
#define NT 4            // B*C trees
#define NN 262144       // nodes per tree (2^18)
#define NPIX (1024*1024)
#define TOTN (NT*NN)            // 1,048,576 nodes total
#define TOTP (NT*NPIX)          // 4,194,304 pixels total

// Jump tables (ping-pong). entry = (ptr, s):
//   ptr = ancestor J levels up (0 = chain terminated at root)
//   s   = float bits of sum of c over the covered path segment (excl. root's c0)
// entry[0] = (0, c0) where c0 = levels[0].
__device__ int2 g_bufA[TOTN];
__device__ int2 g_bufB[TOTN];

__device__ __forceinline__ float sigf(float a, float th) {
    float z = fminf(fmaxf(1000.0f * (a - th), -12.0f), 12.0f);
    return 1.0f / (1.0f + __expf(-z));
}

// ---------------------------------------------------------------------------
// K1 (ILP4): FUSED build of the jump-3 table directly from raw inputs.
// For node i with ancestors p1=parent[i], p2=parent[p1], p3=parent[p2]:
//   entry[i] = (p3, c_i + c_p1 + c_p2), truncated at root (ptr=0).
// entry[0] = (0, levels[0]).  c_j = sigma_j * (levels[j] - levels[parent_j]).
// 3 rounds of 4-wide independent gathers (12/12/4 loads in flight).
// ---------------------------------------------------------------------------
__global__ void k_build3(const float* __restrict__ attr,
                         const float* __restrict__ levels,
                         const float* __restrict__ thr,
                         const int*   __restrict__ parent)
{
    int t = blockIdx.x * blockDim.x + threadIdx.x;
    if (t >= TOTN / 4) return;
    int idx = t * 4;                       // NN % 4 == 0 -> same tree for all 4
    int base = idx & ~(NN - 1);
    int i0 = idx & (NN - 1);

    float4 lv = __ldg(reinterpret_cast<const float4*>(levels) + t);
    float4 at = __ldg(reinterpret_cast<const float4*>(attr) + t);
    int4   pp = __ldg(reinterpret_cast<const int4*>(parent) + t);
    float  th = __ldg(thr);

    float li[4] = {lv.x, lv.y, lv.z, lv.w};
    float ai[4] = {at.x, at.y, at.z, at.w};
    int   p1[4] = {pp.x, pp.y, pp.z, pp.w};

    // round 1: gather parent/attr/levels at p1 (12 independent loads)
    int   p2[4]; float a1[4], l1[4];
#pragma unroll
    for (int k = 0; k < 4; k++) {
        p2[k] = __ldg(&parent[base + p1[k]]);
        a1[k] = __ldg(&attr  [base + p1[k]]);
        l1[k] = __ldg(&levels[base + p1[k]]);
    }
    // round 2: gather at p2 (12 independent loads)
    int   p3[4]; float a2[4], l2[4];
#pragma unroll
    for (int k = 0; k < 4; k++) {
        p3[k] = __ldg(&parent[base + p2[k]]);
        a2[k] = __ldg(&attr  [base + p2[k]]);
        l2[k] = __ldg(&levels[base + p2[k]]);
    }
    // round 3: levels at p3 (4 loads)
    float l3[4];
#pragma unroll
    for (int k = 0; k < 4; k++)
        l3[k] = __ldg(&levels[base + p3[k]]);

    int2 out[4];
#pragma unroll
    for (int k = 0; k < 4; k++) {
        if (i0 + k == 0) {                     // root entry: (0, c0 = levels[0])
            out[k] = make_int2(0, __float_as_int(li[k]));
        } else {
            float s = sigf(ai[k], th) * (li[k] - l1[k]);   // c_i
            int ptr = 0;
            if (p1[k] != 0) {
                s += sigf(a1[k], th) * (l1[k] - l2[k]);    // + c_p1
                if (p2[k] != 0) {
                    s += sigf(a2[k], th) * (l2[k] - l3[k]); // + c_p2
                    ptr = p3[k];
                }
            }
            out[k] = make_int2(ptr, __float_as_int(s));
        }
    }
    reinterpret_cast<int4*>(g_bufA)[t * 2 + 0] = make_int4(out[0].x, out[0].y, out[1].x, out[1].y);
    reinterpret_cast<int4*>(g_bufA)[t * 2 + 1] = make_int4(out[2].x, out[2].y, out[3].x, out[3].y);
}

// ---------------------------------------------------------------------------
// K2 (ILP4): triple pass. out_i = e_i ∘ e[ptr_i] ∘ e[ptr[ptr_i]]
// Turns jump-3 into jump-9 (2 gathers, second dependent).
// ---------------------------------------------------------------------------
__global__ void k_triple(const int2* __restrict__ in, int2* __restrict__ out)
{
    int t = blockIdx.x * blockDim.x + threadIdx.x;
    if (t >= TOTN / 4) return;
    int idx = t * 4;
    int base = idx & ~(NN - 1);

    int4 r0 = __ldg(reinterpret_cast<const int4*>(in) + t * 2 + 0);
    int4 r1 = __ldg(reinterpret_cast<const int4*>(in) + t * 2 + 1);
    int2 e[4] = { make_int2(r0.x, r0.y), make_int2(r0.z, r0.w),
                  make_int2(r1.x, r1.y), make_int2(r1.z, r1.w) };

    int2 b[4];
#pragma unroll
    for (int k = 0; k < 4; k++)
        b[k] = __ldg(&in[base + (e[k].x != 0 ? e[k].x : 0)]);

    int2 c[4];
#pragma unroll
    for (int k = 0; k < 4; k++) {
        int p2 = (e[k].x != 0 && b[k].x != 0) ? b[k].x : 0;
        c[k] = __ldg(&in[base + p2]);
    }

#pragma unroll
    for (int k = 0; k < 4; k++) {
        if (e[k].x != 0) {
            float s2 = __int_as_float(e[k].y) + __int_as_float(b[k].y);
            if (b[k].x != 0) {
                e[k].x = c[k].x;
                e[k].y = __float_as_int(s2 + __int_as_float(c[k].y));
            } else {
                e[k].x = 0;
                e[k].y = __float_as_int(s2);
            }
        }
    }
    reinterpret_cast<int4*>(out)[t * 2 + 0] = make_int4(e[0].x, e[0].y, e[1].x, e[1].y);
    reinterpret_cast<int4*>(out)[t * 2 + 1] = make_int4(e[2].x, e[2].y, e[3].x, e[3].y);
}

// ---------------------------------------------------------------------------
// K3 (ILP4): fused climb + pixel gather over the jump-9 table.
// y[p] = c0 + sum of segment sums starting at node ptn[p].
// ---------------------------------------------------------------------------
__global__ void k_pix(const int2* __restrict__ jp,
                      const int*  __restrict__ ptn,
                      float*      __restrict__ y)
{
    int q = blockIdx.x * blockDim.x + threadIdx.x;   // quad index
    if (q >= TOTP / 4) return;
    int p0 = q * 4;
    int tb = (p0 >> 20) << 18;                       // tree * NN  (NPIX = 2^20)

    float c0 = __int_as_float(__ldg(&jp[tb].y));     // root: c0 = levels[0]
    int4 n = __ldg(reinterpret_cast<const int4*>(ptn) + q);

    int   j[4]   = {n.x, n.y, n.z, n.w};
    float acc[4] = {c0, c0, c0, c0};

    while ((j[0] | j[1] | j[2] | j[3]) != 0) {
        int2 a[4];
#pragma unroll
        for (int k = 0; k < 4; k++)
            a[k] = __ldg(&jp[tb + j[k]]);            // 4 loads in flight
#pragma unroll
        for (int k = 0; k < 4; k++) {
            if (j[k] != 0) {
                acc[k] += __int_as_float(a[k].y);
                j[k] = a[k].x;
            }
        }
    }
    reinterpret_cast<float4*>(y)[q] = make_float4(acc[0], acc[1], acc[2], acc[3]);
}

// ---------------------------------------------------------------------------
extern "C" void kernel_launch(void* const* d_in, const int* in_sizes, int n_in,
                              void* d_out, int out_size)
{
    // metadata order: x, attr_norm, levels, thr, parent, pixel_to_node
    const float* attr   = (const float*)d_in[1];
    const float* levels = (const float*)d_in[2];
    const float* thr    = (const float*)d_in[3];
    const int*   parent = (const int*)d_in[4];
    const int*   ptn    = (const int*)d_in[5];
    float*       y      = (float*)d_out;

    void *pA = nullptr, *pB = nullptr;
    cudaGetSymbolAddress(&pA, g_bufA);
    cudaGetSymbolAddress(&pB, g_bufB);
    int2* A = (int2*)pA;
    int2* B = (int2*)pB;

    const int TPB = 256;
    const int gbN4 = (TOTN / 4) / TPB;

    k_build3<<<gbN4, TPB>>>(attr, levels, thr, parent);   // raw -> jump-3
    k_triple<<<gbN4, TPB>>>(A, B);                        // jump-3 -> jump-9

    const int gbP = (TOTP / 4) / TPB;
    k_pix<<<gbP, TPB>>>(B, ptn, y);
}

// round 8
// speedup vs baseline: 1.7725x; 1.7725x over previous
#include <cuda_runtime.h>
#include <cuda_bf16.h>

// Problem constants (fixed by the dataset)
#define NT 4            // B*C trees
#define NN 262144       // nodes per tree (2^18)
#define NPIX (1024*1024)
#define TOTN (NT*NN)            // 1,048,576 nodes total
#define TOTP (NT*NPIX)          // 4,194,304 pixels total
#define H    8192               // resolved-head size per tree (all ancestors of i<H are <H)

// Jump tables (ping-pong). entry = (ptr, s):
//   ptr = ancestor J levels up (0 = chain terminated at root)
//   s   = float bits of sum of c over the covered path segment (excl. root's c0)
// entry[0] = (0, c0) where c0 = levels[0].
__device__ int2  g_bufA[TOTN];
__device__ int2  g_bufB[TOTN];
__device__ float g_vhead[NT * H];   // fully-resolved v (incl. c0) for nodes < H

// ---------------------------------------------------------------------------
// K1 (ILP4): base jump-1 table. c[i] = sigmoid(clamp(1000*(attr-thr),-12,12))
//            * (levels[i]-levels[p]);  entry[0] = (0, levels[0]).
// ---------------------------------------------------------------------------
__global__ void k_build(const float* __restrict__ attr,
                        const float* __restrict__ levels,
                        const float* __restrict__ thr,
                        const int*   __restrict__ parent)
{
    int t = blockIdx.x * blockDim.x + threadIdx.x;
    if (t >= TOTN / 4) return;
    int idx = t * 4;                       // NN % 4 == 0 -> same tree for all 4
    int base = idx & ~(NN - 1);
    int i0 = idx & (NN - 1);

    float4 lv = __ldg(reinterpret_cast<const float4*>(levels) + t);
    float4 at = __ldg(reinterpret_cast<const float4*>(attr) + t);
    int4   pp = __ldg(reinterpret_cast<const int4*>(parent) + t);
    float  th = __ldg(thr);

    float lp0 = __ldg(&levels[base + pp.x]);
    float lp1 = __ldg(&levels[base + pp.y]);
    float lp2 = __ldg(&levels[base + pp.z]);
    float lp3 = __ldg(&levels[base + pp.w]);

    float l[4] = {lv.x, lv.y, lv.z, lv.w};
    float a[4] = {at.x, at.y, at.z, at.w};
    float lp[4] = {lp0, lp1, lp2, lp3};
    int   p[4] = {pp.x, pp.y, pp.z, pp.w};

    int2 out[4];
#pragma unroll
    for (int k = 0; k < 4; k++) {
        float z = fminf(fmaxf(1000.0f * (a[k] - th), -12.0f), 12.0f);
        float s = 1.0f / (1.0f + __expf(-z));
        float c = s * (l[k] - lp[k]);
        int pk = p[k];
        if (i0 + k == 0) { pk = 0; c = l[k]; }     // root entry: (0, c0)
        out[k] = make_int2(pk, __float_as_int(c));
    }
    reinterpret_cast<int4*>(g_bufA)[t * 2 + 0] = make_int4(out[0].x, out[0].y, out[1].x, out[1].y);
    reinterpret_cast<int4*>(g_bufA)[t * 2 + 1] = make_int4(out[2].x, out[2].y, out[3].x, out[3].y);
}

// ---------------------------------------------------------------------------
// K2 (ILP4): triple pass. out_i = e_i ∘ e[ptr_i] ∘ e[ptr[ptr_i]]
// Turns jump-1 into jump-3 (2 gathers, second dependent).
// ---------------------------------------------------------------------------
__global__ void k_triple(const int2* __restrict__ in, int2* __restrict__ out)
{
    int t = blockIdx.x * blockDim.x + threadIdx.x;
    if (t >= TOTN / 4) return;
    int idx = t * 4;
    int base = idx & ~(NN - 1);

    int4 r0 = __ldg(reinterpret_cast<const int4*>(in) + t * 2 + 0);
    int4 r1 = __ldg(reinterpret_cast<const int4*>(in) + t * 2 + 1);
    int2 e[4] = { make_int2(r0.x, r0.y), make_int2(r0.z, r0.w),
                  make_int2(r1.x, r1.y), make_int2(r1.z, r1.w) };

    int2 b[4];
#pragma unroll
    for (int k = 0; k < 4; k++)
        b[k] = __ldg(&in[base + (e[k].x != 0 ? e[k].x : 0)]);

    int2 c[4];
#pragma unroll
    for (int k = 0; k < 4; k++) {
        int p2 = (e[k].x != 0 && b[k].x != 0) ? b[k].x : 0;
        c[k] = __ldg(&in[base + p2]);
    }

#pragma unroll
    for (int k = 0; k < 4; k++) {
        if (e[k].x != 0) {
            float s2 = __int_as_float(e[k].y) + __int_as_float(b[k].y);
            if (b[k].x != 0) {
                e[k].x = c[k].x;
                e[k].y = __float_as_int(s2 + __int_as_float(c[k].y));
            } else {
                e[k].x = 0;
                e[k].y = __float_as_int(s2);
            }
        }
    }
    reinterpret_cast<int4*>(out)[t * 2 + 0] = make_int4(e[0].x, e[0].y, e[1].x, e[1].y);
    reinterpret_cast<int4*>(out)[t * 2 + 1] = make_int4(e[2].x, e[2].y, e[3].x, e[3].y);
}

// ---------------------------------------------------------------------------
// K3: resolve v fully for nodes < H per tree by climbing the jump-3 table.
// All ancestors of node h<H are <h<H; chain depth ~ ln(H) -> ~3 jump-3 hops.
// The 64KB head region is L2/L1-hot, so this is a tiny kernel.
// v_head[h] = c0 + sum of segment sums along the chain (v_head[0] = c0).
// ---------------------------------------------------------------------------
__global__ void k_head(const int2* __restrict__ jp)
{
    int t = blockIdx.x * blockDim.x + threadIdx.x;
    if (t >= NT * H) return;
    int tr = t >> 13;                   // t / H
    int h  = t & (H - 1);
    int base = tr << 18;                // tr * NN

    float acc = __int_as_float(__ldg(&jp[base].y));   // c0
    int j = h;
    while (j != 0) {
        int2 e = __ldg(&jp[base + j]);
        acc += __int_as_float(e.y);
        j = e.x;
    }
    g_vhead[t] = acc;
}

// ---------------------------------------------------------------------------
// K4 (ILP4): pixel kernel. Climb jump-3 until index < H, then add v_head.
// y[p] = (sum of segment sums while j>=H) + v_head[j]  (v_head includes c0).
// ---------------------------------------------------------------------------
__global__ void k_pix(const int2* __restrict__ jp,
                      const int*  __restrict__ ptn,
                      float*      __restrict__ y)
{
    int q = blockIdx.x * blockDim.x + threadIdx.x;   // quad index
    if (q >= TOTP / 4) return;
    int p0 = q * 4;
    int tr = p0 >> 20;                               // tree  (NPIX = 2^20)
    int tb = tr << 18;                               // tree * NN
    int hb = tr << 13;                               // tree * H

    int4 n = __ldcs(reinterpret_cast<const int4*>(ptn) + q);   // evict-first stream

    int   j[4]   = {n.x, n.y, n.z, n.w};
    float acc[4] = {0.0f, 0.0f, 0.0f, 0.0f};

    while ((j[0] >= H) | (j[1] >= H) | (j[2] >= H) | (j[3] >= H)) {
        int2 a[4];
#pragma unroll
        for (int k = 0; k < 4; k++) {
            int jj = (j[k] >= H) ? j[k] : 0;         // done lanes hit root entry (L1-hot)
            a[k] = __ldg(&jp[tb + jj]);
        }
#pragma unroll
        for (int k = 0; k < 4; k++) {
            if (j[k] >= H) {
                acc[k] += __int_as_float(a[k].y);
                j[k] = a[k].x;
            }
        }
    }
#pragma unroll
    for (int k = 0; k < 4; k++)
        acc[k] += __ldg(&g_vhead[hb + j[k]]);        // hot 32KB table per tree

    reinterpret_cast<float4*>(y)[q] = make_float4(acc[0], acc[1], acc[2], acc[3]);
}

// ---------------------------------------------------------------------------
extern "C" void kernel_launch(void* const* d_in, const int* in_sizes, int n_in,
                              void* d_out, int out_size)
{
    // metadata order: x, attr_norm, levels, thr, parent, pixel_to_node
    const float* attr   = (const float*)d_in[1];
    const float* levels = (const float*)d_in[2];
    const float* thr    = (const float*)d_in[3];
    const int*   parent = (const int*)d_in[4];
    const int*   ptn    = (const int*)d_in[5];
    float*       y      = (float*)d_out;

    void *pA = nullptr, *pB = nullptr;
    cudaGetSymbolAddress(&pA, g_bufA);
    cudaGetSymbolAddress(&pB, g_bufB);
    int2* A = (int2*)pA;
    int2* B = (int2*)pB;

    const int TPB = 256;
    const int gbN4 = (TOTN / 4) / TPB;

    k_build<<<gbN4, TPB>>>(attr, levels, thr, parent);   // raw -> jump-1
    k_triple<<<gbN4, TPB>>>(A, B);                       // jump-1 -> jump-3
    k_head<<<(NT * H) / TPB, TPB>>>(B);                  // resolve v for nodes < H

    const int gbP = (TOTP / 4) / TPB;
    k_pix<<<gbP, TPB>>>(B, ptn, y);
}

// round 9
// speedup vs baseline: 1.9879x; 1.1216x over previous
#include <cuda_runtime.h>
#include <cuda_bf16.h>

// Problem constants (fixed by the dataset)
#define NT 4            // B*C trees
#define NN 262144       // nodes per tree (2^18)
#define NPIX (1024*1024)
#define TOTN (NT*NN)            // 1,048,576 nodes total
#define TOTP (NT*NPIX)          // 4,194,304 pixels total

// Jump tables. entry = (ptr, s):
//   ptr = ancestor J levels up (0 = chain terminated at root)
//   s   = float bits of sum of c over covered segment (excl. root's c0)
// entry[0] = (0, c0) with c0 = levels[0].
__device__ int2  g_bufA[TOTN];
__device__ int2  g_bufB[TOTN];
__device__ float g_v[TOTN];     // fully materialized node values

// ---------------------------------------------------------------------------
// K1 (ILP4): base jump-1 table. c[i] = sigmoid(clamp(1000*(attr-thr),-12,12))
//            * (levels[i]-levels[p]);  entry[0] = (0, levels[0]).
// ---------------------------------------------------------------------------
__global__ void k_build(const float* __restrict__ attr,
                        const float* __restrict__ levels,
                        const float* __restrict__ thr,
                        const int*   __restrict__ parent)
{
    int t = blockIdx.x * blockDim.x + threadIdx.x;
    if (t >= TOTN / 4) return;
    int idx = t * 4;                       // NN % 4 == 0 -> same tree for all 4
    int base = idx & ~(NN - 1);
    int i0 = idx & (NN - 1);

    float4 lv = __ldg(reinterpret_cast<const float4*>(levels) + t);
    float4 at = __ldg(reinterpret_cast<const float4*>(attr) + t);
    int4   pp = __ldg(reinterpret_cast<const int4*>(parent) + t);
    float  th = __ldg(thr);

    float lp0 = __ldg(&levels[base + pp.x]);
    float lp1 = __ldg(&levels[base + pp.y]);
    float lp2 = __ldg(&levels[base + pp.z]);
    float lp3 = __ldg(&levels[base + pp.w]);

    float l[4] = {lv.x, lv.y, lv.z, lv.w};
    float a[4] = {at.x, at.y, at.z, at.w};
    float lp[4] = {lp0, lp1, lp2, lp3};
    int   p[4] = {pp.x, pp.y, pp.z, pp.w};

    int2 out[4];
#pragma unroll
    for (int k = 0; k < 4; k++) {
        float z = fminf(fmaxf(1000.0f * (a[k] - th), -12.0f), 12.0f);
        float s = 1.0f / (1.0f + __expf(-z));
        float c = s * (l[k] - lp[k]);
        int pk = p[k];
        if (i0 + k == 0) { pk = 0; c = l[k]; }     // root entry: (0, c0)
        out[k] = make_int2(pk, __float_as_int(c));
    }
    reinterpret_cast<int4*>(g_bufA)[t * 2 + 0] = make_int4(out[0].x, out[0].y, out[1].x, out[1].y);
    reinterpret_cast<int4*>(g_bufA)[t * 2 + 1] = make_int4(out[2].x, out[2].y, out[3].x, out[3].y);
}

// ---------------------------------------------------------------------------
// K2 (ILP4): triple pass. out_i = e_i ∘ e[ptr_i] ∘ e[ptr[ptr_i]]
// Turns jump-1 into jump-3 (2 gathers, second dependent).
// ---------------------------------------------------------------------------
__global__ void k_triple(const int2* __restrict__ in, int2* __restrict__ out)
{
    int t = blockIdx.x * blockDim.x + threadIdx.x;
    if (t >= TOTN / 4) return;
    int idx = t * 4;
    int base = idx & ~(NN - 1);

    int4 r0 = __ldg(reinterpret_cast<const int4*>(in) + t * 2 + 0);
    int4 r1 = __ldg(reinterpret_cast<const int4*>(in) + t * 2 + 1);
    int2 e[4] = { make_int2(r0.x, r0.y), make_int2(r0.z, r0.w),
                  make_int2(r1.x, r1.y), make_int2(r1.z, r1.w) };

    int2 b[4];
#pragma unroll
    for (int k = 0; k < 4; k++)
        b[k] = __ldg(&in[base + (e[k].x != 0 ? e[k].x : 0)]);

    int2 c[4];
#pragma unroll
    for (int k = 0; k < 4; k++) {
        int p2 = (e[k].x != 0 && b[k].x != 0) ? b[k].x : 0;
        c[k] = __ldg(&in[base + p2]);
    }

#pragma unroll
    for (int k = 0; k < 4; k++) {
        if (e[k].x != 0) {
            float s2 = __int_as_float(e[k].y) + __int_as_float(b[k].y);
            if (b[k].x != 0) {
                e[k].x = c[k].x;
                e[k].y = __float_as_int(s2 + __int_as_float(c[k].y));
            } else {
                e[k].x = 0;
                e[k].y = __float_as_int(s2);
            }
        }
    }
    reinterpret_cast<int4*>(out)[t * 2 + 0] = make_int4(e[0].x, e[0].y, e[1].x, e[1].y);
    reinterpret_cast<int4*>(out)[t * 2 + 1] = make_int4(e[2].x, e[2].y, e[3].x, e[3].y);
}

// ---------------------------------------------------------------------------
// K3 (ILP4): materialize v[] by climbing the jump-3 table.
// v[i] = c0 + s_i + s_{ptr_i} + ...   Own entries are read sequentially
// (vector int4), chain gathers start at own ptr. Rounds >= 3 target tiny
// indices (ln drops ~3/hop) -> few distinct sectors -> cheap wavefronts.
// Adjacent nodes have correlated depths, so max-over-4 waste is small.
// ---------------------------------------------------------------------------
__global__ void k_climb3(const int2* __restrict__ jp)
{
    int t = blockIdx.x * blockDim.x + threadIdx.x;
    if (t >= TOTN / 4) return;
    int idx = t * 4;
    int base = idx & ~(NN - 1);
    int i0 = idx & (NN - 1);

    float c0 = __int_as_float(__ldg(&jp[base].y));   // root's c0 = levels[0]

    int4 r0 = __ldg(reinterpret_cast<const int4*>(jp) + t * 2 + 0);
    int4 r1 = __ldg(reinterpret_cast<const int4*>(jp) + t * 2 + 1);
    int   j[4]   = {r0.x, r0.z, r1.x, r1.z};
    float acc[4] = {__int_as_float(r0.y), __int_as_float(r0.w),
                    __int_as_float(r1.y), __int_as_float(r1.w)};
    if (i0 == 0) { acc[0] = 0.0f; j[0] = 0; }        // node 0: v = c0 only

    while ((j[0] | j[1] | j[2] | j[3]) != 0) {
        int2 a[4];
#pragma unroll
        for (int k = 0; k < 4; k++) {
            int jj = (j[k] != 0) ? j[k] : 0;
            a[k] = __ldg(&jp[base + jj]);
        }
#pragma unroll
        for (int k = 0; k < 4; k++) {
            if (j[k] != 0) {
                acc[k] += __int_as_float(a[k].y);
                j[k] = a[k].x;
            }
        }
    }
#pragma unroll
    for (int k = 0; k < 4; k++) acc[k] += c0;

    reinterpret_cast<float4*>(g_v)[t] = make_float4(acc[0], acc[1], acc[2], acc[3]);
}

// ---------------------------------------------------------------------------
// K4: pixel gather, exactly ONE table lookup per pixel.
// y[p] = v[tree(p)*NN + ptn[p]].  Streams use evict-first hints to keep
// L1 for the v-table's hot head.
// ---------------------------------------------------------------------------
__global__ void k_gather(const int* __restrict__ ptn, float* __restrict__ y)
{
    int q = blockIdx.x * blockDim.x + threadIdx.x;   // quad index
    if (q >= TOTP / 4) return;
    int p0 = q * 4;
    int base = (p0 >> 20) << 18;                     // tree * NN  (NPIX = 2^20)

    int4 n = __ldcs(reinterpret_cast<const int4*>(ptn) + q);
    float4 o;
    o.x = __ldg(&g_v[base + n.x]);
    o.y = __ldg(&g_v[base + n.y]);
    o.z = __ldg(&g_v[base + n.z]);
    o.w = __ldg(&g_v[base + n.w]);
    __stcs(reinterpret_cast<float4*>(y) + q, o);
}

// ---------------------------------------------------------------------------
extern "C" void kernel_launch(void* const* d_in, const int* in_sizes, int n_in,
                              void* d_out, int out_size)
{
    // metadata order: x, attr_norm, levels, thr, parent, pixel_to_node
    const float* attr   = (const float*)d_in[1];
    const float* levels = (const float*)d_in[2];
    const float* thr    = (const float*)d_in[3];
    const int*   parent = (const int*)d_in[4];
    const int*   ptn    = (const int*)d_in[5];
    float*       y      = (float*)d_out;

    void *pA = nullptr, *pB = nullptr;
    cudaGetSymbolAddress(&pA, g_bufA);
    cudaGetSymbolAddress(&pB, g_bufB);
    int2* A = (int2*)pA;
    int2* B = (int2*)pB;

    const int TPB = 256;
    const int gbN4 = (TOTN / 4) / TPB;

    k_build<<<gbN4, TPB>>>(attr, levels, thr, parent);   // raw -> jump-1
    k_triple<<<gbN4, TPB>>>(A, B);                       // jump-1 -> jump-3
    k_climb3<<<gbN4, TPB>>>(B);                          // jump-3 -> full v[]

    const int gbP = (TOTP / 4) / TPB;
    k_gather<<<gbP, TPB>>>(ptn, y);
}